// round 1
// baseline (speedup 1.0000x reference)
#include <cuda_runtime.h>
#include <math.h>
#include <math_constants.h>

#define WINL   400
#define HSHIFT 160
#define NMEL   80
#define NBIN   200     // bins 0..199; bin 200 has zero mel weight
#define FPB    16      // frames per block
#define SPAD   201     // padded spec row (conflict-free LDS)

__device__ float g_window[WINL];
__device__ float g_banks[NMEL * NBIN];
__device__ int   g_Tq[64];

// ---------------------------------------------------------------------------
// Init: Hann window + mel filterbank in fp64 (matches numpy float64 -> f32 cast)
// ---------------------------------------------------------------------------
__global__ void init_tables() {
    int t = blockIdx.x * blockDim.x + threadIdx.x;
    if (t < WINL) {
        double w = 0.5 - 0.5 * cos(2.0 * CUDART_PI * (double)t / (double)(WINL - 1));
        g_window[t] = (float)w;
    }
    for (int i = t; i < NMEL * NBIN; i += gridDim.x * blockDim.x) {
        int m = i / NBIN, k = i - m * NBIN;
        double mlow  = 1127.0 * log(1.0 + 20.0 / 700.0);
        double mhigh = 1127.0 * log(1.0 + 8000.0 / 700.0);
        double d     = (mhigh - mlow) / (double)(NMEL + 1);
        double left  = mlow + (double)m * d;
        double f     = 40.0 * (double)k;          // sr/win * k = 16000/400 * k
        double mel   = 1127.0 * log(1.0 + f / 700.0);
        double up    = (mel - left) / d;
        double down  = (left + 2.0 * d - mel) / d;
        double bk    = fmax(0.0, fmin(up, down));
        g_banks[i] = (float)bk;
    }
}

// ---------------------------------------------------------------------------
// Main fbank kernel: 16 frames per block, 200-bin real DFT, mel + log + norm
// ---------------------------------------------------------------------------
__global__ __launch_bounds__(256) void fbank_kernel(
    const float* __restrict__ x, const float* __restrict__ normalizer,
    float* __restrict__ out, int B, int L, int F)
{
    __shared__ float ysh[WINL * FPB];     // [k][f] layout -> float4 broadcast reads
    __shared__ float spec[FPB * SPAD];    // padded, conflict-free

    const int b     = blockIdx.y;
    const int fbase = blockIdx.x * FPB;
    const int nf    = min(FPB, F - fbase);
    const int tid   = threadIdx.x;

    // ---- framing + pre-emphasis + window -> shared ----
    const float* xb = x + (size_t)b * L;
    for (int i = tid; i < FPB * WINL; i += blockDim.x) {
        int f = i / WINL, k = i - f * WINL;
        float y = 0.f;
        if (f < nf) {
            const float* xp = xb + (size_t)(fbase + f) * HSHIFT;
            float cur = xp[k];
            float pre = k ? xp[k - 1] : cur;
            y = (cur - 0.97f * pre) * g_window[k];
        }
        ysh[k * FPB + f] = y;
    }
    __syncthreads();

    // ---- 400-point real DFT, bins 0..199, 16 frames per thread ----
    if (tid < NBIN) {
        const int bin = tid;
        float re[FPB], im[FPB];
        #pragma unroll
        for (int f = 0; f < FPB; f++) { re[f] = 0.f; im[f] = 0.f; }

        const float4* y4 = (const float4*)ysh;
        const float step = 6.283185307179586f / 400.0f;
        int p = 0;                                  // (bin*k) mod 400
        for (int k = 0; k < WINL; k++) {
            int pc = p; if (pc > 200) pc -= 400;    // arg in [-pi, pi]
            float s, c;
            __sincosf((float)pc * step, &s, &c);
            #pragma unroll
            for (int j = 0; j < 4; j++) {
                float4 a = y4[k * 4 + j];
                re[4*j+0] += a.x * c;  im[4*j+0] += a.x * s;
                re[4*j+1] += a.y * c;  im[4*j+1] += a.y * s;
                re[4*j+2] += a.z * c;  im[4*j+2] += a.z * s;
                re[4*j+3] += a.w * c;  im[4*j+3] += a.w * s;
            }
            p += bin; if (p >= 400) p -= 400;
        }
        #pragma unroll
        for (int f = 0; f < FPB; f++)
            spec[f * SPAD + bin] = re[f] * re[f] + im[f] * im[f];
    }
    __syncthreads();

    // ---- mel projection + log + normalize + store ----
    const float EPSF = 2.2204460492503131e-16f;
    const int tot = nf * NMEL;
    for (int i = tid; i < tot; i += blockDim.x) {
        int m = i / nf, f = i - m * nf;   // m ~uniform per warp -> bank row broadcast
        const float* bank = g_banks + m * NBIN;
        const float* sp   = spec + f * SPAD;
        float acc = 0.f;
        #pragma unroll 4
        for (int k = 0; k < NBIN; k++) acc += sp[k] * __ldg(bank + k);
        float v = logf(fmaxf(acc, EPSF)) * __ldg(normalizer + m);
        out[((size_t)b * F + (fbase + f)) * NMEL + m] = v;
    }
}

// ---------------------------------------------------------------------------
// T quantization: ds = f32(maxT)/80 ; T_ = int(f32(T)/ds)   (IEEE f32 div)
// ---------------------------------------------------------------------------
__global__ void tq_kernel(const int* __restrict__ T, int B) {
    __shared__ int sh[64];
    int t = threadIdx.x;
    int v = (t < B) ? T[t] : 1;
    sh[t] = v;
    __syncthreads();
    for (int off = 32; off > 0; off >>= 1) {
        if (t < off) sh[t] = max(sh[t], sh[t + off]);
        __syncthreads();
    }
    if (t < B) {
        float ds = __fdiv_rn((float)sh[0], (float)NMEL);
        g_Tq[t] = (int)__fdiv_rn((float)v, ds);
    }
}

// ---------------------------------------------------------------------------
// Masked mean subtraction, in-place on out. T_ <= 80 so the sum is short.
// ---------------------------------------------------------------------------
__global__ __launch_bounds__(256) void meansub_kernel(float* __restrict__ out, int F) {
    __shared__ float part[3][NMEL];
    __shared__ float smean[NMEL];
    const int b  = blockIdx.x;
    const int tq = g_Tq[b];
    const int t  = threadIdx.x;
    float* ob = out + (size_t)b * F * NMEL;

    if (t < 3 * NMEL) {
        int m = t % NMEL, s = t / NMEL;
        float acc = 0.f;
        for (int f = s; f < tq; f += 3) acc += ob[(size_t)f * NMEL + m];
        part[s][m] = acc;
    }
    __syncthreads();
    if (t < NMEL)
        smean[t] = (part[0][t] + part[1][t] + part[2][t]) / (float)max(tq, 1);
    __syncthreads();

    const int n = tq * NMEL;
    for (int i = t; i < n; i += blockDim.x)
        ob[i] -= smean[i % NMEL];
}

// ---------------------------------------------------------------------------
extern "C" void kernel_launch(void* const* d_in, const int* in_sizes, int n_in,
                              void* d_out, int out_size) {
    const float* x   = (const float*)d_in[0];
    const int*   T   = (const int*)d_in[1];
    const float* nrm = (const float*)d_in[2];
    float* out = (float*)d_out;

    int B = in_sizes[1];
    int L = in_sizes[0] / B;
    int F = 1 + (L - WINL) / HSHIFT;

    init_tables<<<64, 256>>>();

    dim3 grid((F + FPB - 1) / FPB, B);
    fbank_kernel<<<grid, 256>>>(x, nrm, out, B, L, F);

    tq_kernel<<<1, 64>>>(T, B);
    meansub_kernel<<<B, 256>>>(out, F);
}

// round 2
// speedup vs baseline: 2.3189x; 2.3189x over previous
#include <cuda_runtime.h>
#include <math.h>
#include <math_constants.h>

#define WINL    400
#define HSHIFT  160
#define NMEL    80
#define NBIN    200      // bins 0..199; bin 200 has zero mel weight
#define FPB     16       // frames per block
#define SPAD    216      // padded spec row
#define YSTR    20       // padded frame stride in ysh / S planes
#define TWO_PI  6.283185307179586476

__device__ float g_window[WINL];
__device__ float g_banks[NMEL * NBIN];   // dense (built once, feeds sparse)
__device__ float g_melw[NMEL * 16];      // sparse mel weights (16-wide padded)
__device__ int   g_melk0[NMEL];          // first bin of each mel row
__device__ int   g_Tq[64];

// ---------------------------------------------------------------------------
// Init: Hann window + dense mel filterbank in fp64
// ---------------------------------------------------------------------------
__global__ void init_tables() {
    int t = blockIdx.x * blockDim.x + threadIdx.x;
    if (t < WINL) {
        double w = 0.5 - 0.5 * cos(2.0 * CUDART_PI * (double)t / (double)(WINL - 1));
        g_window[t] = (float)w;
    }
    for (int i = t; i < NMEL * NBIN; i += gridDim.x * blockDim.x) {
        int m = i / NBIN, k = i - m * NBIN;
        double mlow  = 1127.0 * log(1.0 + 20.0 / 700.0);
        double mhigh = 1127.0 * log(1.0 + 8000.0 / 700.0);
        double d     = (mhigh - mlow) / (double)(NMEL + 1);
        double left  = mlow + (double)m * d;
        double f     = 40.0 * (double)k;
        double mel   = 1127.0 * log(1.0 + f / 700.0);
        double up    = (mel - left) / d;
        double down  = (left + 2.0 * d - mel) / d;
        g_banks[i]   = (float)fmax(0.0, fmin(up, down));
    }
}

// Build sparse mel rows (support is <= 13 contiguous bins; pad to 16)
__global__ void build_sparse() {
    int m = threadIdx.x;
    if (m >= NMEL) return;
    int k0 = 0;
    while (k0 < NBIN && g_banks[m * NBIN + k0] == 0.f) k0++;
    if (k0 > NBIN - 16) k0 = NBIN - 16;
    g_melk0[m] = k0;
    for (int j = 0; j < 16; j++) {
        int k = k0 + j;
        g_melw[m * 16 + j] = (k < NBIN) ? g_banks[m * NBIN + k] : 0.f;
    }
}

// ---------------------------------------------------------------------------
// fbank: framing -> 20x20 factorized real DFT -> power -> sparse mel -> log
// ---------------------------------------------------------------------------
__global__ __launch_bounds__(256, 2) void fbank_kernel(
    const float* __restrict__ x, const float* __restrict__ nrm,
    float* __restrict__ out, int B, int L, int F)
{
    extern __shared__ float sm[];
    float* ysh  = sm;              // 400 * 20 = 8000 floats, [k][f] padded
    float* Sre  = sm + 8000;       // 11 * 20 * 20 = 4400
    float* Sim  = sm + 12400;      // 4400
    float* spec = sm;              // alias ysh after stage 1: [f*216 + k]

    const int b     = blockIdx.y;
    const int fbase = blockIdx.x * FPB;
    const int nf    = min(FPB, F - fbase);
    const int tid   = threadIdx.x;

    // ---- framing + pre-emphasis + window ----
    const float* xb = x + (size_t)b * L;
    for (int i = tid; i < FPB * WINL; i += 256) {
        int f = i / WINL, k = i - f * WINL;
        float y = 0.f;
        if (f < nf) {
            const float* xp = xb + (size_t)(fbase + f) * HSHIFT;
            float cur = xp[k];
            float pre = k ? xp[k - 1] : cur;
            y = (cur - 0.97f * pre) * g_window[k];
        }
        ysh[k * YSTR + f] = y;
    }
    __syncthreads();

    // ---- stage 1: S[b1][k2] = sum_k1 y[k2+20*k1] * e^{+2pi i b1 k1/20},
    //      b1 = 0..10 only (conjugate symmetry). Threads: 6 b1-pairs x 20 k2.
    if (tid < 120) {
        int p = tid / 20, k2 = tid - 20 * p;
        int b1a = 2 * p, b1b = 2 * p + 1;
        bool hasB = (b1b <= 10);
        float stA_s, stA_c, stB_s, stB_c;
        __sincosf((float)(TWO_PI / 20.0) * (float)b1a, &stA_s, &stA_c);
        __sincosf((float)(TWO_PI / 20.0) * (float)b1b, &stB_s, &stB_c);
        float cA = 1.f, sA = 0.f, cB = 1.f, sB = 0.f;

        float rA[16], iA[16], rB[16], iB[16];
        #pragma unroll
        for (int f = 0; f < 16; f++) { rA[f] = iA[f] = rB[f] = iB[f] = 0.f; }

        for (int k1 = 0; k1 < 20; k1++) {
            const float4* yrow = (const float4*)(ysh + (k2 + 20 * k1) * YSTR);
            #pragma unroll
            for (int j = 0; j < 4; j++) {
                float4 a = yrow[j];
                rA[4*j+0] += a.x * cA;  iA[4*j+0] += a.x * sA;
                rA[4*j+1] += a.y * cA;  iA[4*j+1] += a.y * sA;
                rA[4*j+2] += a.z * cA;  iA[4*j+2] += a.z * sA;
                rA[4*j+3] += a.w * cA;  iA[4*j+3] += a.w * sA;
                rB[4*j+0] += a.x * cB;  iB[4*j+0] += a.x * sB;
                rB[4*j+1] += a.y * cB;  iB[4*j+1] += a.y * sB;
                rB[4*j+2] += a.z * cB;  iB[4*j+2] += a.z * sB;
                rB[4*j+3] += a.w * cB;  iB[4*j+3] += a.w * sB;
            }
            float t;
            t = cA * stA_c - sA * stA_s; sA = cA * stA_s + sA * stA_c; cA = t;
            t = cB * stB_c - sB * stB_s; sB = cB * stB_s + sB * stB_c; cB = t;
        }
        int offA = (b1a * 20 + k2) * YSTR;
        float4* dr = (float4*)(Sre + offA);
        float4* di = (float4*)(Sim + offA);
        #pragma unroll
        for (int j = 0; j < 4; j++) {
            dr[j] = make_float4(rA[4*j], rA[4*j+1], rA[4*j+2], rA[4*j+3]);
            di[j] = make_float4(iA[4*j], iA[4*j+1], iA[4*j+2], iA[4*j+3]);
        }
        if (hasB) {
            int offB = (b1b * 20 + k2) * YSTR;
            float4* dr2 = (float4*)(Sre + offB);
            float4* di2 = (float4*)(Sim + offB);
            #pragma unroll
            for (int j = 0; j < 4; j++) {
                dr2[j] = make_float4(rB[4*j], rB[4*j+1], rB[4*j+2], rB[4*j+3]);
                di2[j] = make_float4(iB[4*j], iB[4*j+1], iB[4*j+2], iB[4*j+3]);
            }
        }
    }
    __syncthreads();

    // ---- stage 2: X[b] = sum_k2 S[b mod 20][k2] * e^{+2pi i b k2/400}
    //      thread = (b1: 20, b2-pair: 5, frame-half: 2); 2 bins x 8 frames.
    if (tid < 200) {
        int b1  = tid / 10, q = tid - 10 * b1;
        int b2g = q >> 1, fh = q & 1;
        int b1r = (b1 <= 10) ? b1 : 20 - b1;
        float csg = (b1 <= 10) ? 1.f : -1.f;     // conjugate for b1 > 10
        int bA = b1 + 40 * b2g, bB = bA + 20;

        float stA_s, stA_c, stB_s, stB_c;
        __sincosf((float)(TWO_PI / 400.0) * (float)bA, &stA_s, &stA_c);
        __sincosf((float)(TWO_PI / 400.0) * (float)bB, &stB_s, &stB_c);
        float cA = 1.f, sA = 0.f, cB = 1.f, sB = 0.f;

        float rAa[8], iAa[8], rBa[8], iBa[8];
        #pragma unroll
        for (int f = 0; f < 8; f++) { rAa[f] = iAa[f] = rBa[f] = iBa[f] = 0.f; }

        for (int k2 = 0; k2 < 20; k2++) {
            int base = (b1r * 20 + k2) * YSTR + fh * 8;
            float4 r0 = ((const float4*)(Sre + base))[0];
            float4 r1 = ((const float4*)(Sre + base))[1];
            float4 m0 = ((const float4*)(Sim + base))[0];
            float4 m1 = ((const float4*)(Sim + base))[1];
            float srv[8] = { r0.x, r0.y, r0.z, r0.w, r1.x, r1.y, r1.z, r1.w };
            float siv[8] = { m0.x * csg, m0.y * csg, m0.z * csg, m0.w * csg,
                             m1.x * csg, m1.y * csg, m1.z * csg, m1.w * csg };
            #pragma unroll
            for (int f = 0; f < 8; f++) {
                rAa[f] += srv[f] * cA - siv[f] * sA;
                iAa[f] += srv[f] * sA + siv[f] * cA;
                rBa[f] += srv[f] * cB - siv[f] * sB;
                iBa[f] += srv[f] * sB + siv[f] * cB;
            }
            float t;
            t = cA * stA_c - sA * stA_s; sA = cA * stA_s + sA * stA_c; cA = t;
            t = cB * stB_c - sB * stB_s; sB = cB * stB_s + sB * stB_c; cB = t;
        }
        int fb = fh * 8;
        #pragma unroll
        for (int f = 0; f < 8; f++) {
            spec[(fb + f) * SPAD + bA] = rAa[f] * rAa[f] + iAa[f] * iAa[f];
            spec[(fb + f) * SPAD + bB] = rBa[f] * rBa[f] + iBa[f] * iBa[f];
        }
    }
    __syncthreads();

    // ---- sparse mel + log + normalize ----
    const float EPSF = 2.2204460492503131e-16f;
    for (int i = tid; i < nf * NMEL; i += 256) {
        int f = i / NMEL, m = i - f * NMEL;
        const float* w  = g_melw + m * 16;
        const float* sp = spec + f * SPAD + g_melk0[m];
        float acc = 0.f;
        #pragma unroll
        for (int j = 0; j < 16; j++) acc += sp[j] * __ldg(w + j);
        out[((size_t)b * F + (fbase + f)) * NMEL + m] =
            logf(fmaxf(acc, EPSF)) * __ldg(nrm + m);
    }
}

// ---------------------------------------------------------------------------
// T quantization: ds = f32(maxT)/80 ; T_ = int(f32(T)/ds)
// ---------------------------------------------------------------------------
__global__ void tq_kernel(const int* __restrict__ T, int B) {
    __shared__ int sh[64];
    int t = threadIdx.x;
    int v = (t < B) ? T[t] : 1;
    sh[t] = v;
    __syncthreads();
    for (int off = 32; off > 0; off >>= 1) {
        if (t < off) sh[t] = max(sh[t], sh[t + off]);
        __syncthreads();
    }
    if (t < B) {
        float ds = __fdiv_rn((float)sh[0], (float)NMEL);
        g_Tq[t] = (int)__fdiv_rn((float)v, ds);
    }
}

// ---------------------------------------------------------------------------
// Masked mean subtraction, in-place. T_ <= 80.
// ---------------------------------------------------------------------------
__global__ __launch_bounds__(256) void meansub_kernel(float* __restrict__ out, int F) {
    __shared__ float part[3][NMEL];
    __shared__ float smean[NMEL];
    const int b  = blockIdx.x;
    const int tq = g_Tq[b];
    const int t  = threadIdx.x;
    float* ob = out + (size_t)b * F * NMEL;

    if (t < 3 * NMEL) {
        int m = t % NMEL, s = t / NMEL;
        float acc = 0.f;
        for (int f = s; f < tq; f += 3) acc += ob[(size_t)f * NMEL + m];
        part[s][m] = acc;
    }
    __syncthreads();
    if (t < NMEL)
        smean[t] = (part[0][t] + part[1][t] + part[2][t]) / (float)max(tq, 1);
    __syncthreads();

    const int n = tq * NMEL;
    for (int i = t; i < n; i += blockDim.x)
        ob[i] -= smean[i % NMEL];
}

// ---------------------------------------------------------------------------
extern "C" void kernel_launch(void* const* d_in, const int* in_sizes, int n_in,
                              void* d_out, int out_size) {
    const float* x   = (const float*)d_in[0];
    const int*   T   = (const int*)d_in[1];
    const float* nrm = (const float*)d_in[2];
    float* out = (float*)d_out;

    int B = in_sizes[1];
    int L = in_sizes[0] / B;
    int F = 1 + (L - WINL) / HSHIFT;

    static int smem_set = 0;
    const int SMEM_BYTES = 16800 * 4;
    if (!smem_set) {
        cudaFuncSetAttribute(fbank_kernel,
                             cudaFuncAttributeMaxDynamicSharedMemorySize, SMEM_BYTES);
        smem_set = 1;
    }

    init_tables<<<64, 256>>>();
    build_sparse<<<1, 128>>>();

    dim3 grid((F + FPB - 1) / FPB, B);
    fbank_kernel<<<grid, 256, SMEM_BYTES>>>(x, nrm, out, B, L, F);

    tq_kernel<<<1, 64>>>(T, B);
    meansub_kernel<<<B, 256>>>(out, F);
}

// round 3
// speedup vs baseline: 3.1351x; 1.3520x over previous
#include <cuda_runtime.h>
#include <math.h>
#include <math_constants.h>

#define WINL    400
#define HSHIFT  160
#define NMEL    80
#define NBIN    200      // bins 0..199; bin 200 has zero mel weight
#define FPB     16       // frames per block
#define SPAD    213      // padded spec row: 213 mod 32 = 21 (odd) -> conflict-free
#define YSTR    20       // frame stride in ysh / S planes
#define TWO_PI  6.283185307179586476

__device__ float  g_window[WINL];
__device__ float  g_banks[NMEL * NBIN];
__device__ float  g_melw[NMEL * 16];
__device__ int    g_melk0[NMEL];
__device__ float2 g_tw1[11 * 20];        // e^{+2pi i b1 k1 / 20},  b1=0..10
__device__ float2 g_tw2[NBIN * 20];      // (cos, sgn*sin) of 2pi b k2 / 400

// ---------------------------------------------------------------------------
// Init: window, dense mel banks, both twiddle tables (all fp64 -> f32)
// ---------------------------------------------------------------------------
__global__ void init_tables() {
    int t = blockIdx.x * blockDim.x + threadIdx.x;
    if (t < WINL) {
        double w = 0.5 - 0.5 * cos(2.0 * CUDART_PI * (double)t / (double)(WINL - 1));
        g_window[t] = (float)w;
    }
    if (t < 11 * 20) {
        int b1 = t / 20, k1 = t - 20 * b1;
        double a = TWO_PI * (double)(b1 * k1) / 20.0;
        g_tw1[t] = make_float2((float)cos(a), (float)sin(a));
    }
    if (t < NBIN * 20) {
        int b = t / 20, k2 = t - 20 * b;
        int b1m = b % 20;
        double sgn = (b1m <= 10) ? 1.0 : -1.0;
        double a = TWO_PI * (double)b * (double)k2 / 400.0;
        g_tw2[t] = make_float2((float)cos(a), (float)(sgn * sin(a)));
    }
    for (int i = t; i < NMEL * NBIN; i += gridDim.x * blockDim.x) {
        int m = i / NBIN, k = i - m * NBIN;
        double mlow  = 1127.0 * log(1.0 + 20.0 / 700.0);
        double mhigh = 1127.0 * log(1.0 + 8000.0 / 700.0);
        double d     = (mhigh - mlow) / (double)(NMEL + 1);
        double left  = mlow + (double)m * d;
        double f     = 40.0 * (double)k;
        double mel   = 1127.0 * log(1.0 + f / 700.0);
        double up    = (mel - left) / d;
        double down  = (left + 2.0 * d - mel) / d;
        g_banks[i]   = (float)fmax(0.0, fmin(up, down));
    }
}

// Sparse mel rows (support <= 13 contiguous bins; pad to 16)
__global__ void build_sparse() {
    int m = threadIdx.x;
    if (m >= NMEL) return;
    int k0 = 0;
    while (k0 < NBIN && g_banks[m * NBIN + k0] == 0.f) k0++;
    if (k0 > NBIN - 16) k0 = NBIN - 16;
    g_melk0[m] = k0;
    for (int j = 0; j < 16; j++) {
        int k = k0 + j;
        g_melw[m * 16 + j] = (k < NBIN) ? g_banks[m * NBIN + k] : 0.f;
    }
}

// ---------------------------------------------------------------------------
// fbank: framing -> 20x20 factorized real DFT (table twiddles) -> sparse mel
// ---------------------------------------------------------------------------
__global__ __launch_bounds__(256, 2) void fbank_kernel(
    const float* __restrict__ x, const float* __restrict__ nrm,
    float* __restrict__ out, int B, int L, int F)
{
    extern __shared__ float sm[];
    float* ysh  = sm;              // 400*20 = 8000 floats, [k][f]
    float* Sre  = sm + 8000;       // 11*20*20 = 4400
    float* Sim  = sm + 12400;      // 4400
    float* spec = sm;              // alias ysh after stage 1: [f*SPAD + k]

    const int b     = blockIdx.y;
    const int fbase = blockIdx.x * FPB;
    const int nf    = min(FPB, F - fbase);
    const int tid   = threadIdx.x;

    // ---- framing + pre-emphasis + window (division-free) ----
    const float* xb = x + (size_t)b * L;
    #pragma unroll
    for (int f = 0; f < FPB; f++) {
        const float* xp = xb + (size_t)(fbase + f) * HSHIFT;
        bool live = (f < nf);
        for (int k = tid; k < WINL; k += 256) {
            float y = 0.f;
            if (live) {
                float cur = xp[k];
                float pre = k ? xp[k - 1] : cur;
                y = (cur - 0.97f * pre) * g_window[k];
            }
            ysh[k * YSTR + f] = y;
        }
    }
    __syncthreads();

    // ---- stage 1: S[b1][k2][f] = sum_k1 y[k2+20k1][f] * e^{+2pi i b1 k1/20}
    //      220 threads: (b1: 0..10) x (k2: 0..19); 16 frames, 32 accumulators.
    if (tid < 220) {
        const int b1 = tid / 20, k2 = tid - 20 * b1;
        float re[FPB], im[FPB];
        #pragma unroll
        for (int f = 0; f < FPB; f++) { re[f] = 0.f; im[f] = 0.f; }

        const float2* tw = g_tw1 + b1 * 20;
        #pragma unroll 5
        for (int k1 = 0; k1 < 20; k1++) {
            float2 w = __ldg(tw + k1);
            const float4* yrow = (const float4*)(ysh + (k2 + 20 * k1) * YSTR);
            #pragma unroll
            for (int j = 0; j < 4; j++) {
                float4 a = yrow[j];
                re[4*j+0] += a.x * w.x;  im[4*j+0] += a.x * w.y;
                re[4*j+1] += a.y * w.x;  im[4*j+1] += a.y * w.y;
                re[4*j+2] += a.z * w.x;  im[4*j+2] += a.z * w.y;
                re[4*j+3] += a.w * w.x;  im[4*j+3] += a.w * w.y;
            }
        }
        const int off = (b1 * 20 + k2) * YSTR;
        float4* dr = (float4*)(Sre + off);
        float4* di = (float4*)(Sim + off);
        #pragma unroll
        for (int j = 0; j < 4; j++) {
            dr[j] = make_float4(re[4*j], re[4*j+1], re[4*j+2], re[4*j+3]);
            di[j] = make_float4(im[4*j], im[4*j+1], im[4*j+2], im[4*j+3]);
        }
    }
    __syncthreads();

    // ---- stage 2: X[b][f] = sum_k2 S[b%20][k2][f] * e^{+2pi i b k2/400}
    //      200 threads: (b1: 0..19) x (b2g: 0..4) x (fh: 0..1)
    //      each: 2 bins {b1+40*b2g, +20} x 8 frames. Conjugate sign folded
    //      into g_tw2 sine (|X|^2 is invariant to global conjugation).
    if (tid < 200) {
        const int b1  = tid / 10, q = tid - 10 * b1;
        const int b2g = q >> 1, fh = q & 1;
        const int b1r = (b1 <= 10) ? b1 : 20 - b1;
        const int bA  = b1 + 40 * b2g, bB = bA + 20;

        float rA[8], iA[8], rB[8], iB[8];
        #pragma unroll
        for (int f = 0; f < 8; f++) { rA[f] = iA[f] = rB[f] = iB[f] = 0.f; }

        const float2* twA = g_tw2 + bA * 20;
        const float2* twB = g_tw2 + bB * 20;
        #pragma unroll 5
        for (int k2 = 0; k2 < 20; k2++) {
            const int base = (b1r * 20 + k2) * YSTR + fh * 8;
            float4 r0 = ((const float4*)(Sre + base))[0];
            float4 r1 = ((const float4*)(Sre + base))[1];
            float4 m0 = ((const float4*)(Sim + base))[0];
            float4 m1 = ((const float4*)(Sim + base))[1];
            float2 wA = __ldg(twA + k2);
            float2 wB = __ldg(twB + k2);
            float sr[8] = { r0.x, r0.y, r0.z, r0.w, r1.x, r1.y, r1.z, r1.w };
            float si[8] = { m0.x, m0.y, m0.z, m0.w, m1.x, m1.y, m1.z, m1.w };
            #pragma unroll
            for (int f = 0; f < 8; f++) {
                rA[f] += sr[f] * wA.x - si[f] * wA.y;
                iA[f] += sr[f] * wA.y + si[f] * wA.x;
                rB[f] += sr[f] * wB.x - si[f] * wB.y;
                iB[f] += sr[f] * wB.y + si[f] * wB.x;
            }
        }
        const int fb = fh * 8;
        #pragma unroll
        for (int f = 0; f < 8; f++) {
            spec[(fb + f) * SPAD + bA] = rA[f] * rA[f] + iA[f] * iA[f];
            spec[(fb + f) * SPAD + bB] = rB[f] * rB[f] + iB[f] * iB[f];
        }
    }
    __syncthreads();

    // ---- sparse mel + log + normalize (division-free mapping) ----
    const float EPSF = 2.2204460492503131e-16f;
    const int f  = tid & 15;
    const int mb = tid >> 4;
    if (f < nf) {
        #pragma unroll
        for (int j = 0; j < 5; j++) {
            const int m = mb + 16 * j;
            const float* w  = g_melw + m * 16;
            const float* sp = spec + f * SPAD + g_melk0[m];
            float acc = 0.f;
            #pragma unroll
            for (int t = 0; t < 16; t++) acc += sp[t] * __ldg(w + t);
            out[((size_t)b * F + (fbase + f)) * NMEL + m] =
                __logf(fmaxf(acc, EPSF)) * __ldg(nrm + m);
        }
    }
}

// ---------------------------------------------------------------------------
// Masked mean subtraction (tq computed inline). T_ <= 80.
// ---------------------------------------------------------------------------
__global__ __launch_bounds__(256) void meansub_kernel(
    const int* __restrict__ T, float* __restrict__ out, int F, int B)
{
    __shared__ int   shT[64];
    __shared__ float part[3][NMEL];
    __shared__ float smean[NMEL];
    __shared__ int   shTq;

    const int b = blockIdx.x;
    const int t = threadIdx.x;

    if (t < 64) shT[t] = (t < B) ? T[t] : 1;
    __syncthreads();
    if (t < 32) shT[t] = max(shT[t], shT[t + 32]);
    __syncthreads();
    if (t == 0) {
        int mx = shT[0];
        #pragma unroll
        for (int i = 1; i < 32; i++) mx = max(mx, shT[i]);
        float ds = __fdiv_rn((float)mx, (float)NMEL);
        shTq = (int)__fdiv_rn((float)T[b], ds);
    }
    __syncthreads();
    const int tq = shTq;
    float* ob = out + (size_t)b * F * NMEL;

    if (t < 3 * NMEL) {
        int m = t % NMEL, s = t / NMEL;
        float acc = 0.f;
        for (int f = s; f < tq; f += 3) acc += ob[(size_t)f * NMEL + m];
        part[s][m] = acc;
    }
    __syncthreads();
    if (t < NMEL)
        smean[t] = (part[0][t] + part[1][t] + part[2][t]) / (float)max(tq, 1);
    __syncthreads();

    const int n = tq * NMEL;
    for (int i = t; i < n; i += blockDim.x)
        ob[i] -= smean[i % NMEL];
}

// ---------------------------------------------------------------------------
extern "C" void kernel_launch(void* const* d_in, const int* in_sizes, int n_in,
                              void* d_out, int out_size) {
    const float* x   = (const float*)d_in[0];
    const int*   T   = (const int*)d_in[1];
    const float* nrm = (const float*)d_in[2];
    float* out = (float*)d_out;

    int B = in_sizes[1];
    int L = in_sizes[0] / B;
    int F = 1 + (L - WINL) / HSHIFT;

    static int smem_set = 0;
    const int SMEM_BYTES = 16800 * 4;
    if (!smem_set) {
        cudaFuncSetAttribute(fbank_kernel,
                             cudaFuncAttributeMaxDynamicSharedMemorySize, SMEM_BYTES);
        smem_set = 1;
    }

    init_tables<<<64, 256>>>();
    build_sparse<<<1, 128>>>();

    dim3 grid((F + FPB - 1) / FPB, B);
    fbank_kernel<<<grid, 256, SMEM_BYTES>>>(x, nrm, out, B, L, F);

    meansub_kernel<<<B, 256>>>(T, out, F, B);
}

// round 4
// speedup vs baseline: 3.2986x; 1.0522x over previous
#include <cuda_runtime.h>
#include <math.h>
#include <math_constants.h>

#define WINL    400
#define HSHIFT  160
#define NMEL    80
#define NBIN    200      // bins 0..199; bin 200 has zero mel weight
#define FPB     16       // frames per block
#define SPAD    213      // padded spec row (odd stride -> conflict-free)
#define YSTR    20       // frame stride in ysh rows
#define SPLANE  404      // padded b1-plane stride in S (404 words = 101 chunks)
#define TWO_PI  6.283185307179586476

__device__ float  g_window[WINL];
__device__ float  g_banks[NMEL * NBIN];
__device__ float  g_melw[NMEL * 16];
__device__ int    g_melk0[NMEL];
__device__ float2 g_tw1[11 * 20];        // e^{+2pi i b1 k1 / 20},  b1=0..10
__device__ float2 g_tw2[NBIN * 20];      // (cos, sgn*sin) of 2pi b k2 / 400
__device__ int    g_Tq[64];

// ---------------------------------------------------------------------------
// Init kernels (split so the ncu skip-5 capture lands on fbank_kernel)
// ---------------------------------------------------------------------------
__global__ void init_win_tw1() {
    int t = blockIdx.x * blockDim.x + threadIdx.x;
    if (t < WINL) {
        double w = 0.5 - 0.5 * cos(2.0 * CUDART_PI * (double)t / (double)(WINL - 1));
        g_window[t] = (float)w;
    }
    if (t < 11 * 20) {
        int b1 = t / 20, k1 = t - 20 * b1;
        double a = TWO_PI * (double)(b1 * k1) / 20.0;
        g_tw1[t] = make_float2((float)cos(a), (float)sin(a));
    }
}

__global__ void init_tw2() {
    int t = blockIdx.x * blockDim.x + threadIdx.x;
    if (t < NBIN * 20) {
        int b = t / 20, k2 = t - 20 * b;
        int b1m = b % 20;
        double sgn = (b1m <= 10) ? 1.0 : -1.0;   // conjugate fold for b1 > 10
        double a = TWO_PI * (double)b * (double)k2 / 400.0;
        g_tw2[t] = make_float2((float)cos(a), (float)(sgn * sin(a)));
    }
}

__global__ void init_banks() {
    int t = blockIdx.x * blockDim.x + threadIdx.x;
    for (int i = t; i < NMEL * NBIN; i += gridDim.x * blockDim.x) {
        int m = i / NBIN, k = i - m * NBIN;
        double mlow  = 1127.0 * log(1.0 + 20.0 / 700.0);
        double mhigh = 1127.0 * log(1.0 + 8000.0 / 700.0);
        double d     = (mhigh - mlow) / (double)(NMEL + 1);
        double left  = mlow + (double)m * d;
        double f     = 40.0 * (double)k;
        double mel   = 1127.0 * log(1.0 + f / 700.0);
        double up    = (mel - left) / d;
        double down  = (left + 2.0 * d - mel) / d;
        g_banks[i]   = (float)fmax(0.0, fmin(up, down));
    }
}

__global__ void build_sparse() {
    int m = threadIdx.x;
    if (m >= NMEL) return;
    int k0 = 0;
    while (k0 < NBIN && g_banks[m * NBIN + k0] == 0.f) k0++;
    if (k0 > NBIN - 16) k0 = NBIN - 16;
    g_melk0[m] = k0;
    for (int j = 0; j < 16; j++) {
        int k = k0 + j;
        g_melw[m * 16 + j] = (k < NBIN) ? g_banks[m * NBIN + k] : 0.f;
    }
}

__global__ void tq_kernel(const int* __restrict__ T, int B) {
    __shared__ int sh[64];
    int t = threadIdx.x;
    int v = (t < B) ? T[t] : 1;
    sh[t] = v;
    __syncthreads();
    for (int off = 32; off > 0; off >>= 1) {
        if (t < off) sh[t] = max(sh[t], sh[t + off]);
        __syncthreads();
    }
    if (t < B) {
        float ds = __fdiv_rn((float)sh[0], (float)NMEL);
        g_Tq[t] = (int)__fdiv_rn((float)v, ds);
    }
}

// ---------------------------------------------------------------------------
// fbank: framing -> 20x20 factorized real DFT (table twiddles) -> sparse mel
// ---------------------------------------------------------------------------
__global__ __launch_bounds__(256, 3) void fbank_kernel(
    const float* __restrict__ x, const float* __restrict__ nrm,
    float* __restrict__ out, int B, int L, int F)
{
    extern __shared__ float sm[];
    float* ysh  = sm;              // 400*20 = 8000 floats, [k][f]
    float* Sre  = sm + 8000;       // 11 planes * 404 = 4440
    float* Sim  = sm + 12440;      // 4440
    float* spec = sm;              // alias ysh after stage 1: [f*SPAD + k]

    const int b     = blockIdx.y;
    const int fbase = blockIdx.x * FPB;
    const int nf    = min(FPB, F - fbase);
    const int tid   = threadIdx.x;

    // ---- framing + pre-emphasis + window ----
    const float* xb = x + (size_t)b * L;
    #pragma unroll
    for (int f = 0; f < FPB; f++) {
        const float* xp = xb + (size_t)(fbase + f) * HSHIFT;
        bool live = (f < nf);
        for (int k = tid; k < WINL; k += 256) {
            float y = 0.f;
            if (live) {
                float cur = xp[k];
                float pre = k ? xp[k - 1] : cur;
                y = (cur - 0.97f * pre) * g_window[k];
            }
            ysh[k * YSTR + f] = y;
        }
    }
    __syncthreads();

    // ---- stage 1: S[b1][k2][f] = sum_k1 y[k2+20k1][f] * tw1[b1][k1]
    //      220 threads: (b1: 0..10) x (k2: 0..19); 16 frames each.
    if (tid < 220) {
        const int b1 = tid / 20, k2 = tid - 20 * b1;
        float re[FPB], im[FPB];
        #pragma unroll
        for (int f = 0; f < FPB; f++) { re[f] = 0.f; im[f] = 0.f; }

        const float2* tw = g_tw1 + b1 * 20;
        #pragma unroll 5
        for (int k1 = 0; k1 < 20; k1++) {
            float2 w = __ldg(tw + k1);
            const float4* yrow = (const float4*)(ysh + (k2 + 20 * k1) * YSTR);
            #pragma unroll
            for (int j = 0; j < 4; j++) {
                float4 a = yrow[j];
                re[4*j+0] += a.x * w.x;  im[4*j+0] += a.x * w.y;
                re[4*j+1] += a.y * w.x;  im[4*j+1] += a.y * w.y;
                re[4*j+2] += a.z * w.x;  im[4*j+2] += a.z * w.y;
                re[4*j+3] += a.w * w.x;  im[4*j+3] += a.w * w.y;
            }
        }
        const int off = b1 * SPLANE + k2 * YSTR;
        float4* dr = (float4*)(Sre + off);
        float4* di = (float4*)(Sim + off);
        #pragma unroll
        for (int j = 0; j < 4; j++) {
            dr[j] = make_float4(re[4*j], re[4*j+1], re[4*j+2], re[4*j+3]);
            di[j] = make_float4(im[4*j], im[4*j+1], im[4*j+2], im[4*j+3]);
        }
    }
    __syncthreads();

    // ---- stage 2: X[b][f] = sum_k2 S[b%20][k2][f] * tw2[b][k2]
    //      200 threads: (b1: 0..19) x (b2g: 0..4) x (fh: 0..1);
    //      2 bins {b1+40*b2g, +20} x 8 frames each.
    if (tid < 200) {
        const int b1  = tid / 10, q = tid - 10 * b1;
        const int b2g = q >> 1, fh = q & 1;
        const int b1r = (b1 <= 10) ? b1 : 20 - b1;
        const int bA  = b1 + 40 * b2g, bB = bA + 20;

        float rA[8], iA[8], rB[8], iB[8];
        #pragma unroll
        for (int f = 0; f < 8; f++) { rA[f] = iA[f] = rB[f] = iB[f] = 0.f; }

        const float2* twA = g_tw2 + bA * 20;
        const float2* twB = g_tw2 + bB * 20;
        #pragma unroll 5
        for (int k2 = 0; k2 < 20; k2++) {
            const int base = b1r * SPLANE + k2 * YSTR + fh * 8;
            float4 r0 = ((const float4*)(Sre + base))[0];
            float4 r1 = ((const float4*)(Sre + base))[1];
            float4 m0 = ((const float4*)(Sim + base))[0];
            float4 m1 = ((const float4*)(Sim + base))[1];
            float2 wA = __ldg(twA + k2);
            float2 wB = __ldg(twB + k2);
            float sr[8] = { r0.x, r0.y, r0.z, r0.w, r1.x, r1.y, r1.z, r1.w };
            float si[8] = { m0.x, m0.y, m0.z, m0.w, m1.x, m1.y, m1.z, m1.w };
            #pragma unroll
            for (int f = 0; f < 8; f++) {
                rA[f] += sr[f] * wA.x - si[f] * wA.y;
                iA[f] += sr[f] * wA.y + si[f] * wA.x;
                rB[f] += sr[f] * wB.x - si[f] * wB.y;
                iB[f] += sr[f] * wB.y + si[f] * wB.x;
            }
        }
        const int fb = fh * 8;
        #pragma unroll
        for (int f = 0; f < 8; f++) {
            spec[(fb + f) * SPAD + bA] = rA[f] * rA[f] + iA[f] * iA[f];
            spec[(fb + f) * SPAD + bB] = rB[f] * rB[f] + iB[f] * iB[f];
        }
    }
    __syncthreads();

    // ---- sparse mel + log + normalize ----
    const float EPSF = 2.2204460492503131e-16f;
    const int f  = tid & 15;
    const int mb = tid >> 4;
    if (f < nf) {
        #pragma unroll
        for (int j = 0; j < 5; j++) {
            const int m = mb + 16 * j;
            const float* w  = g_melw + m * 16;
            const float* sp = spec + f * SPAD + g_melk0[m];
            float acc = 0.f;
            #pragma unroll
            for (int t = 0; t < 16; t++) acc += sp[t] * __ldg(w + t);
            out[((size_t)b * F + (fbase + f)) * NMEL + m] =
                __logf(fmaxf(acc, EPSF)) * __ldg(nrm + m);
        }
    }
}

// ---------------------------------------------------------------------------
// Masked mean subtraction, in-place. T_ <= 80.
// ---------------------------------------------------------------------------
__global__ __launch_bounds__(256) void meansub_kernel(float* __restrict__ out, int F) {
    __shared__ float part[3][NMEL];
    __shared__ float smean[NMEL];
    const int b  = blockIdx.x;
    const int tq = g_Tq[b];
    const int t  = threadIdx.x;
    float* ob = out + (size_t)b * F * NMEL;

    if (t < 3 * NMEL) {
        int m = t % NMEL, s = t / NMEL;
        float acc = 0.f;
        for (int f = s; f < tq; f += 3) acc += ob[(size_t)f * NMEL + m];
        part[s][m] = acc;
    }
    __syncthreads();
    if (t < NMEL)
        smean[t] = (part[0][t] + part[1][t] + part[2][t]) / (float)max(tq, 1);
    __syncthreads();

    const int n = tq * NMEL;
    for (int i = t; i < n; i += blockDim.x)
        ob[i] -= smean[i % NMEL];
}

// ---------------------------------------------------------------------------
extern "C" void kernel_launch(void* const* d_in, const int* in_sizes, int n_in,
                              void* d_out, int out_size) {
    const float* x   = (const float*)d_in[0];
    const int*   T   = (const int*)d_in[1];
    const float* nrm = (const float*)d_in[2];
    float* out = (float*)d_out;

    int B = in_sizes[1];
    int L = in_sizes[0] / B;
    int F = 1 + (L - WINL) / HSHIFT;

    static int smem_set = 0;
    const int SMEM_BYTES = 16880 * 4;   // ysh 8000 + 2 * 4440
    if (!smem_set) {
        cudaFuncSetAttribute(fbank_kernel,
                             cudaFuncAttributeMaxDynamicSharedMemorySize, SMEM_BYTES);
        smem_set = 1;
    }

    // 5 small setup launches, then fbank is launch #6 (ncu -s 5 -c 1 captures it)
    init_win_tw1<<<4, 256>>>();
    init_tw2<<<16, 256>>>();
    init_banks<<<64, 256>>>();
    build_sparse<<<1, 128>>>();
    tq_kernel<<<1, 64>>>(T, B);

    dim3 grid((F + FPB - 1) / FPB, B);
    fbank_kernel<<<grid, 256, SMEM_BYTES>>>(x, nrm, out, B, L, F);

    meansub_kernel<<<B, 256>>>(out, F);
}